// round 1
// baseline (speedup 1.0000x reference)
#include <cuda_runtime.h>
#include <math.h>

#define B_SZ    128
#define G_CNT   10000
#define KWID    20
#define C_OUT   3
#define LATD    2000
#define GC      30000     // G*C
#define IN_LEN  200000
#define NSPLIT  8

// scratch (no allocations allowed -> __device__ globals)
__device__ float g_h[B_SZ * GC];               // encoder conv output  (15.36 MB)
__device__ float g_part[NSPLIT * B_SZ * LATD]; // FC1 split-K partials ( 8.2 MB)
__device__ float g_z[B_SZ * LATD];             // latent               ( 1.0 MB)
__device__ float g_d[B_SZ * GC];               // decoder FC output    (15.36 MB)

__device__ __forceinline__ float lrelu(float x) { return x >= 0.0f ? x : 0.1f * x; }

// ---------------------------------------------------------------------------
// Kernel 1: grouped encoder conv  h[b,g,c] = lrelu(sum_k x[b,g*20+k]*w[g,c,k] + b[g,c])
// ---------------------------------------------------------------------------
__global__ __launch_bounds__(256) void enc_conv_k(
    const float* __restrict__ x, const float* __restrict__ w, const float* __restrict__ bias)
{
    int idx = blockIdx.x * blockDim.x + threadIdx.x;
    if (idx >= B_SZ * G_CNT) return;
    int b = idx / G_CNT, g = idx % G_CNT;

    const float4* xp = (const float4*)(x + (size_t)b * IN_LEN + g * KWID);
    float xv[20];
#pragma unroll
    for (int i = 0; i < 5; i++) {
        float4 t = xp[i];
        xv[4*i+0] = t.x; xv[4*i+1] = t.y; xv[4*i+2] = t.z; xv[4*i+3] = t.w;
    }
    const float* wp = w + (size_t)g * (C_OUT * KWID);
    float* hp = g_h + (size_t)b * GC + (size_t)g * C_OUT;
#pragma unroll
    for (int c = 0; c < C_OUT; c++) {
        const float4* wc = (const float4*)(wp + c * KWID);
        float acc = bias[g * C_OUT + c];
#pragma unroll
        for (int i = 0; i < 5; i++) {
            float4 t = wc[i];
            acc = fmaf(xv[4*i+0], t.x, acc);
            acc = fmaf(xv[4*i+1], t.y, acc);
            acc = fmaf(xv[4*i+2], t.z, acc);
            acc = fmaf(xv[4*i+3], t.w, acc);
        }
        hp[c] = lrelu(acc);
    }
}

// ---------------------------------------------------------------------------
// FC GEMM:  C[m,n] = sum_k A[m,k] * W[n,k]   (A row-major [128,K], W row-major [N,K])
// Block tile: 128(M) x 64(N), BK=8, 256 threads, per-thread 8x4 outputs with
// m-pairs packed into f32x2 lanes -> 16 fma.rn.f32x2 per k per thread.
// which==0: A=g_h, write raw split-K partials to g_part (grid.y = split)
// which==1: A=g_z, fused bias+leaky, write g_d
// ---------------------------------------------------------------------------
__global__ __launch_bounds__(256) void fc_gemm_k(
    int which, const float* __restrict__ W, const float* __restrict__ bias,
    int N, int K, int steps_total, int steps_per_split)
{
    __shared__ float As[8][132];   // [k][m], padded
    __shared__ float Bs[8][68];    // [k][n], padded

    const float* __restrict__ A = (which == 0) ? g_h : g_z;
    float* __restrict__ out     = (which == 0) ? g_part : g_d;

    const int tid = threadIdx.x;
    const int tm  = tid >> 4;    // 0..15  (m-group: rows tm*8 .. tm*8+7)
    const int tn  = tid & 15;    // 0..15  (n-group: cols tn*4 .. tn*4+3)
    const int nbase = blockIdx.x * 64;
    const int sp    = blockIdx.y;

    int st    = sp * steps_per_split;
    int stend = st + steps_per_split;
    if (stend > steps_total) stend = steps_total;

    unsigned long long acc[4][4];
#pragma unroll
    for (int i = 0; i < 4; i++)
#pragma unroll
        for (int j = 0; j < 4; j++) acc[i][j] = 0ull;

    const int arow = tid >> 1;          // 0..127
    const int akq4 = (tid & 1) * 4;     // 0 or 4
    const int ng   = nbase + arow;      // for B loads (tid<128)
    const bool bld = (tid < 128);
    const bool bok = bld && (ng < N);

    for (; st < stend; ++st) {
        const int k0 = st * 8;
        float4 av = *(const float4*)(A + (size_t)arow * K + k0 + akq4);
        float4 bv = make_float4(0.f, 0.f, 0.f, 0.f);
        if (bok) bv = *(const float4*)(W + (size_t)ng * K + k0 + akq4);

        __syncthreads();   // previous iteration's reads done
        As[akq4 + 0][arow] = av.x;
        As[akq4 + 1][arow] = av.y;
        As[akq4 + 2][arow] = av.z;
        As[akq4 + 3][arow] = av.w;
        if (bld) {
            Bs[akq4 + 0][arow] = bv.x;
            Bs[akq4 + 1][arow] = bv.y;
            Bs[akq4 + 2][arow] = bv.z;
            Bs[akq4 + 3][arow] = bv.w;
        }
        __syncthreads();

#pragma unroll
        for (int kk = 0; kk < 8; kk++) {
            const float* ar = &As[kk][tm * 8];
            ulonglong2 a01 = *(const ulonglong2*)(ar);
            ulonglong2 a23 = *(const ulonglong2*)(ar + 4);
            unsigned long long am[4];
            am[0] = a01.x; am[1] = a01.y; am[2] = a23.x; am[3] = a23.y;

            float4 bvv = *(const float4*)&Bs[kk][tn * 4];
            unsigned long long bb[4];
            {
                unsigned int u;
                u = __float_as_uint(bvv.x);
                asm("mov.b64 %0, {%1, %1};" : "=l"(bb[0]) : "r"(u));
                u = __float_as_uint(bvv.y);
                asm("mov.b64 %0, {%1, %1};" : "=l"(bb[1]) : "r"(u));
                u = __float_as_uint(bvv.z);
                asm("mov.b64 %0, {%1, %1};" : "=l"(bb[2]) : "r"(u));
                u = __float_as_uint(bvv.w);
                asm("mov.b64 %0, {%1, %1};" : "=l"(bb[3]) : "r"(u));
            }
#pragma unroll
            for (int i = 0; i < 4; i++)
#pragma unroll
                for (int j = 0; j < 4; j++)
                    asm("fma.rn.f32x2 %0, %1, %2, %0;"
                        : "+l"(acc[i][j]) : "l"(am[i]), "l"(bb[j]));
        }
    }

    // epilogue
#pragma unroll
    for (int i = 0; i < 4; i++) {
        const int m0 = tm * 8 + 2 * i;   // pair rows m0, m0+1 (lo, hi lanes)
#pragma unroll
        for (int j = 0; j < 4; j++) {
            const int n = nbase + tn * 4 + j;
            if (n >= N) continue;
            unsigned int lo, hi;
            asm("mov.b64 {%0, %1}, %2;" : "=r"(lo), "=r"(hi) : "l"(acc[i][j]));
            float flo = __uint_as_float(lo);
            float fhi = __uint_as_float(hi);
            if (which == 1) {
                float bz = bias[n];
                out[(size_t)m0 * N + n]       = lrelu(flo + bz);
                out[(size_t)(m0 + 1) * N + n] = lrelu(fhi + bz);
            } else {
                size_t base = ((size_t)(sp * B_SZ + m0)) * N + n;
                out[base]     = flo;
                out[base + N] = fhi;
            }
        }
    }
}

// ---------------------------------------------------------------------------
// Kernel 3: FC1 split-K reduction + bias + leaky -> g_z
// ---------------------------------------------------------------------------
__global__ __launch_bounds__(256) void fc1_red_k(const float* __restrict__ bias)
{
    int idx = blockIdx.x * blockDim.x + threadIdx.x;
    if (idx >= B_SZ * LATD) return;
    int m = idx / LATD, n = idx % LATD;
    float s = bias[n];
#pragma unroll
    for (int sp = 0; sp < NSPLIT; sp++)
        s += g_part[((size_t)(sp * B_SZ + m)) * LATD + n];
    g_z[(size_t)m * LATD + n] = lrelu(s);
}

// ---------------------------------------------------------------------------
// Kernel 5: grouped conv-transpose + sigmoid
// out[b,g,k] = sigmoid(sum_c d[b,g,c]*w[g,c,k] + dec_b[g])
// ---------------------------------------------------------------------------
__global__ __launch_bounds__(256) void dec_conv_k(
    const float* __restrict__ w, const float* __restrict__ bias, float* __restrict__ out)
{
    int idx = blockIdx.x * blockDim.x + threadIdx.x;
    if (idx >= B_SZ * G_CNT) return;
    int b = idx / G_CNT, g = idx % G_CNT;

    const float* dp = g_d + (size_t)b * GC + (size_t)g * C_OUT;
    float d0 = dp[0], d1 = dp[1], d2 = dp[2];
    const float* wp = w + (size_t)g * (C_OUT * KWID);
    float bz = bias[g];

    float o[20];
#pragma unroll
    for (int i = 0; i < 5; i++) {
        float4 w0 = ((const float4*)(wp))[i];
        float4 w1 = ((const float4*)(wp + 20))[i];
        float4 w2 = ((const float4*)(wp + 40))[i];
        float v;
        v = fmaf(d0, w0.x, fmaf(d1, w1.x, fmaf(d2, w2.x, bz))); o[4*i+0] = v;
        v = fmaf(d0, w0.y, fmaf(d1, w1.y, fmaf(d2, w2.y, bz))); o[4*i+1] = v;
        v = fmaf(d0, w0.z, fmaf(d1, w1.z, fmaf(d2, w2.z, bz))); o[4*i+2] = v;
        v = fmaf(d0, w0.w, fmaf(d1, w1.w, fmaf(d2, w2.w, bz))); o[4*i+3] = v;
    }
    float4* op = (float4*)(out + (size_t)b * IN_LEN + g * KWID);
#pragma unroll
    for (int i = 0; i < 5; i++) {
        float4 r;
        r.x = 1.0f / (1.0f + expf(-o[4*i+0]));
        r.y = 1.0f / (1.0f + expf(-o[4*i+1]));
        r.z = 1.0f / (1.0f + expf(-o[4*i+2]));
        r.w = 1.0f / (1.0f + expf(-o[4*i+3]));
        op[i] = r;
    }
}

// ---------------------------------------------------------------------------
extern "C" void kernel_launch(void* const* d_in, const int* in_sizes, int n_in,
                              void* d_out, int out_size)
{
    const float* x        = (const float*)d_in[0];
    const float* enc_w    = (const float*)d_in[1];
    const float* enc_b    = (const float*)d_in[2];
    const float* enc_fc_w = (const float*)d_in[3];
    const float* enc_fc_b = (const float*)d_in[4];
    const float* dec_fc_w = (const float*)d_in[5];
    const float* dec_fc_b = (const float*)d_in[6];
    const float* dec_w    = (const float*)d_in[7];
    const float* dec_b    = (const float*)d_in[8];
    float* out = (float*)d_out;

    // 1) encoder grouped conv
    enc_conv_k<<<(B_SZ * G_CNT + 255) / 256, 256>>>(x, enc_w, enc_b);

    // 2) FC1: [128,30000] @ [2000,30000]^T, split-K=8 (3750 BK-steps -> 469/split)
    {
        dim3 grid((LATD + 63) / 64, NSPLIT);
        fc_gemm_k<<<grid, 256>>>(0, enc_fc_w, nullptr, LATD, GC, GC / 8, 469);
    }

    // 3) reduce split-K partials + bias + leaky -> z
    fc1_red_k<<<(B_SZ * LATD + 255) / 256, 256>>>(enc_fc_b);

    // 4) FC2: [128,2000] @ [30000,2000]^T, fused bias+leaky -> d
    {
        dim3 grid((GC + 63) / 64, 1);
        fc_gemm_k<<<grid, 256>>>(1, dec_fc_w, dec_fc_b, GC, LATD, LATD / 8, LATD / 8);
    }

    // 5) decoder grouped conv-transpose + sigmoid
    dec_conv_k<<<(B_SZ * G_CNT + 255) / 256, 256>>>(dec_w, dec_b, out);
}

// round 5
// speedup vs baseline: 1.2966x; 1.2966x over previous
#include <cuda_runtime.h>
#include <math.h>
#include <stdint.h>

#define B_SZ    128
#define G_CNT   10000
#define KWID    20
#define C_OUT   3
#define LATD    2000
#define GC      30000
#define IN_LEN  200000
#define NSPLIT1 16

// scratch (__device__ globals; no allocations allowed)
__device__ float g_h[B_SZ * GC];               // encoder conv out (15.36 MB)
__device__ float g_part[NSPLIT1 * B_SZ * LATD]; // FC1 split-K partials (16.4 MB)
__device__ float g_z[B_SZ * LATD];             // latent
__device__ float g_d[B_SZ * GC];               // decoder FC out

__device__ __forceinline__ float lrelu(float x) { return x >= 0.0f ? x : 0.1f * x; }

__device__ __forceinline__ void split_tf32(float x, uint32_t& hi, uint32_t& lo) {
    asm("cvt.rna.tf32.f32 %0, %1;" : "=r"(hi) : "f"(x));
    float r = x - __uint_as_float(hi);
    asm("cvt.rna.tf32.f32 %0, %1;" : "=r"(lo) : "f"(r));
}

__device__ __forceinline__ void mma_tf32(float c[4], const uint32_t a[4], const uint32_t b[2]) {
    asm volatile(
        "mma.sync.aligned.m16n8k8.row.col.f32.tf32.tf32.f32 "
        "{%0,%1,%2,%3}, {%4,%5,%6,%7}, {%8,%9}, {%0,%1,%2,%3};"
        : "+f"(c[0]), "+f"(c[1]), "+f"(c[2]), "+f"(c[3])
        : "r"(a[0]), "r"(a[1]), "r"(a[2]), "r"(a[3]), "r"(b[0]), "r"(b[1]));
}

// ---------------------------------------------------------------------------
// Kernel 1: grouped encoder conv  h[b,g,c] = lrelu(sum_k x[b,g*20+k]*w[g,c,k]+b)
// ---------------------------------------------------------------------------
__global__ __launch_bounds__(256) void enc_conv_k(
    const float* __restrict__ x, const float* __restrict__ w, const float* __restrict__ bias)
{
    int idx = blockIdx.x * blockDim.x + threadIdx.x;
    if (idx >= B_SZ * G_CNT) return;
    int b = idx / G_CNT, g = idx % G_CNT;

    const float4* xp = (const float4*)(x + (size_t)b * IN_LEN + g * KWID);
    float xv[20];
#pragma unroll
    for (int i = 0; i < 5; i++) {
        float4 t = xp[i];
        xv[4*i+0] = t.x; xv[4*i+1] = t.y; xv[4*i+2] = t.z; xv[4*i+3] = t.w;
    }
    const float* wp = w + (size_t)g * (C_OUT * KWID);
    float* hp = g_h + (size_t)b * GC + (size_t)g * C_OUT;
#pragma unroll
    for (int c = 0; c < C_OUT; c++) {
        const float4* wc = (const float4*)(wp + c * KWID);
        float acc = bias[g * C_OUT + c];
#pragma unroll
        for (int i = 0; i < 5; i++) {
            float4 t = wc[i];
            acc = fmaf(xv[4*i+0], t.x, acc);
            acc = fmaf(xv[4*i+1], t.y, acc);
            acc = fmaf(xv[4*i+2], t.z, acc);
            acc = fmaf(xv[4*i+3], t.w, acc);
        }
        hp[c] = lrelu(acc);
    }
}

// ---------------------------------------------------------------------------
// FC GEMM via mma.sync tf32 (3xTF32 split -> fp32-class accuracy).
// C[m,n] = sum_k A[m,k]*W[n,k]; A row-major [128,K], W row-major [N,K].
// Block tile 128(M) x 128(N), BK=16, 256 threads = 8 warps (2x4).
// fuse==0: write raw split-K partials to g_part[(sp*128+m)*N+n]  (FC1)
// fuse==1: write lrelu(acc + bias[n]) to g_d                      (FC2)
// which: 0 -> A=g_h, 1 -> A=g_z
// ---------------------------------------------------------------------------
__global__ __launch_bounds__(256) void fc_mma_k(
    int which, const float* __restrict__ W, const float* __restrict__ bias,
    int N, int K, int steps_total, int steps_per_split, int fuse)
{
    __shared__ uint32_t Ah[16][136], Al[16][136];
    __shared__ uint32_t Wh[16][136], Wl[16][136];

    const float* __restrict__ A = (which == 0) ? g_h : g_z;

    const int tid = threadIdx.x;
    const int nbase = blockIdx.x * 128;
    const int sp = blockIdx.y;
    int s0 = sp * steps_per_split;
    int s1 = s0 + steps_per_split;
    if (s1 > steps_total) s1 = steps_total;

    const int warp = tid >> 5, lane = tid & 31;
    const int wm = (warp >> 2) * 64;   // 0 or 64
    const int wn = (warp & 3) * 32;    // 0..96
    const int g = lane >> 2, tig = lane & 3;

    float acc[4][4][4];
#pragma unroll
    for (int mt = 0; mt < 4; mt++)
#pragma unroll
        for (int nt = 0; nt < 4; nt++)
#pragma unroll
            for (int v = 0; v < 4; v++) acc[mt][nt][v] = 0.0f;

    float4 ra[2], rw[2];
    const int row_a = tid >> 2;      // 0..63 (+64 for i=1)
    const int q_a   = tid & 3;       // k-quad

    {
        int k0 = s0 * 16;
#pragma unroll
        for (int i = 0; i < 2; i++) {
            int row = row_a + i * 64;
            ra[i] = *(const float4*)(A + (size_t)row * K + k0 + q_a * 4);
            int wr = nbase + row;
            rw[i] = (wr < N) ? *(const float4*)(W + (size_t)wr * K + k0 + q_a * 4)
                             : make_float4(0.f, 0.f, 0.f, 0.f);
        }
    }

    for (int st = s0; st < s1; ++st) {
        __syncthreads();
#pragma unroll
        for (int i = 0; i < 2; i++) {
            int row = row_a + i * 64;
            float va[4] = { ra[i].x, ra[i].y, ra[i].z, ra[i].w };
            float vw[4] = { rw[i].x, rw[i].y, rw[i].z, rw[i].w };
#pragma unroll
            for (int j = 0; j < 4; j++) {
                uint32_t hi, lo;
                split_tf32(va[j], hi, lo);
                Ah[q_a * 4 + j][row] = hi;
                Al[q_a * 4 + j][row] = lo;
                split_tf32(vw[j], hi, lo);
                Wh[q_a * 4 + j][row] = hi;
                Wl[q_a * 4 + j][row] = lo;
            }
        }
        __syncthreads();

        if (st + 1 < s1) {
            int k0 = (st + 1) * 16;
#pragma unroll
            for (int i = 0; i < 2; i++) {
                int row = row_a + i * 64;
                ra[i] = *(const float4*)(A + (size_t)row * K + k0 + q_a * 4);
                int wr = nbase + row;
                rw[i] = (wr < N) ? *(const float4*)(W + (size_t)wr * K + k0 + q_a * 4)
                                 : make_float4(0.f, 0.f, 0.f, 0.f);
            }
        }

#pragma unroll
        for (int kk = 0; kk < 2; kk++) {
            const int k = kk * 8;
            uint32_t bh[4][2], bl[4][2];
#pragma unroll
            for (int nt = 0; nt < 4; nt++) {
                int n = wn + nt * 8 + g;
                bh[nt][0] = Wh[k + tig][n];
                bh[nt][1] = Wh[k + tig + 4][n];
                bl[nt][0] = Wl[k + tig][n];
                bl[nt][1] = Wl[k + tig + 4][n];
            }
#pragma unroll
            for (int mt = 0; mt < 4; mt++) {
                int m = wm + mt * 16 + g;
                uint32_t ah[4], al[4];
                ah[0] = Ah[k + tig][m];     ah[1] = Ah[k + tig][m + 8];
                ah[2] = Ah[k + tig + 4][m]; ah[3] = Ah[k + tig + 4][m + 8];
                al[0] = Al[k + tig][m];     al[1] = Al[k + tig][m + 8];
                al[2] = Al[k + tig + 4][m]; al[3] = Al[k + tig + 4][m + 8];
#pragma unroll
                for (int nt = 0; nt < 4; nt++) {
                    mma_tf32(acc[mt][nt], ah, bh[nt]);
                    mma_tf32(acc[mt][nt], al, bh[nt]);
                    mma_tf32(acc[mt][nt], ah, bl[nt]);
                }
            }
        }
    }

    // epilogue
#pragma unroll
    for (int mt = 0; mt < 4; mt++) {
        int m0 = wm + mt * 16 + g;
#pragma unroll
        for (int nt = 0; nt < 4; nt++) {
            int n = nbase + wn + nt * 8 + tig * 2;
            if (n >= N) continue;
            if (fuse) {
                float b0 = bias[n], b1 = bias[n + 1];
                float2 v0, v1;
                v0.x = lrelu(acc[mt][nt][0] + b0);
                v0.y = lrelu(acc[mt][nt][1] + b1);
                v1.x = lrelu(acc[mt][nt][2] + b0);
                v1.y = lrelu(acc[mt][nt][3] + b1);
                *(float2*)(g_d + (size_t)m0 * N + n) = v0;
                *(float2*)(g_d + (size_t)(m0 + 8) * N + n) = v1;
            } else {
                size_t base = ((size_t)(sp * B_SZ + m0)) * N + n;
                float2 v0; v0.x = acc[mt][nt][0]; v0.y = acc[mt][nt][1];
                float2 v1; v1.x = acc[mt][nt][2]; v1.y = acc[mt][nt][3];
                *(float2*)(g_part + base) = v0;
                *(float2*)(g_part + base + (size_t)8 * N) = v1;
            }
        }
    }
}

// ---------------------------------------------------------------------------
// FC1 split-K reduction + bias + leaky -> g_z
// ---------------------------------------------------------------------------
__global__ __launch_bounds__(256) void red_k(const float* __restrict__ bias)
{
    int idx = blockIdx.x * blockDim.x + threadIdx.x;
    if (idx >= B_SZ * LATD) return;
    int m = idx / LATD, n = idx % LATD;
    float s = bias[n];
#pragma unroll
    for (int sp = 0; sp < NSPLIT1; sp++)
        s += g_part[((size_t)(sp * B_SZ + m)) * LATD + n];
    g_z[(size_t)m * LATD + n] = lrelu(s);
}

// ---------------------------------------------------------------------------
// Kernel 5: grouped conv-transpose + sigmoid
// ---------------------------------------------------------------------------
__global__ __launch_bounds__(256) void dec_conv_k(
    const float* __restrict__ w, const float* __restrict__ bias, float* __restrict__ out)
{
    int idx = blockIdx.x * blockDim.x + threadIdx.x;
    if (idx >= B_SZ * G_CNT) return;
    int b = idx / G_CNT, g = idx % G_CNT;

    const float* dp = g_d + (size_t)b * GC + (size_t)g * C_OUT;
    float d0 = dp[0], d1 = dp[1], d2 = dp[2];
    const float* wp = w + (size_t)g * (C_OUT * KWID);
    float bz = bias[g];

    float o[20];
#pragma unroll
    for (int i = 0; i < 5; i++) {
        float4 w0 = ((const float4*)(wp))[i];
        float4 w1 = ((const float4*)(wp + 20))[i];
        float4 w2 = ((const float4*)(wp + 40))[i];
        float v;
        v = fmaf(d0, w0.x, fmaf(d1, w1.x, fmaf(d2, w2.x, bz))); o[4*i+0] = v;
        v = fmaf(d0, w0.y, fmaf(d1, w1.y, fmaf(d2, w2.y, bz))); o[4*i+1] = v;
        v = fmaf(d0, w0.z, fmaf(d1, w1.z, fmaf(d2, w2.z, bz))); o[4*i+2] = v;
        v = fmaf(d0, w0.w, fmaf(d1, w1.w, fmaf(d2, w2.w, bz))); o[4*i+3] = v;
    }
    float4* op = (float4*)(out + (size_t)b * IN_LEN + g * KWID);
#pragma unroll
    for (int i = 0; i < 5; i++) {
        float4 r;
        r.x = 1.0f / (1.0f + expf(-o[4*i+0]));
        r.y = 1.0f / (1.0f + expf(-o[4*i+1]));
        r.z = 1.0f / (1.0f + expf(-o[4*i+2]));
        r.w = 1.0f / (1.0f + expf(-o[4*i+3]));
        op[i] = r;
    }
}

// ---------------------------------------------------------------------------
extern "C" void kernel_launch(void* const* d_in, const int* in_sizes, int n_in,
                              void* d_out, int out_size)
{
    const float* x        = (const float*)d_in[0];
    const float* enc_w    = (const float*)d_in[1];
    const float* enc_b    = (const float*)d_in[2];
    const float* enc_fc_w = (const float*)d_in[3];
    const float* enc_fc_b = (const float*)d_in[4];
    const float* dec_fc_w = (const float*)d_in[5];
    const float* dec_fc_b = (const float*)d_in[6];
    const float* dec_w    = (const float*)d_in[7];
    const float* dec_b    = (const float*)d_in[8];
    float* out = (float*)d_out;

    // 1) encoder grouped conv -> g_h
    enc_conv_k<<<(B_SZ * G_CNT + 255) / 256, 256>>>(x, enc_w, enc_b);

    // 2) FC1: [128,30000]@[2000,30000]^T. steps=1875, split-K=16 (118/split)
    {
        dim3 grid((LATD + 127) / 128, NSPLIT1);
        fc_mma_k<<<grid, 256>>>(0, enc_fc_w, nullptr, LATD, GC, 1875, 118, 0);
    }
    // 3) reduce + bias + leaky -> g_z
    red_k<<<(B_SZ * LATD + 255) / 256, 256>>>(enc_fc_b);

    // 4) FC2: [128,2000]@[30000,2000]^T. steps=125, split=1, fused epilogue -> g_d
    {
        dim3 grid((GC + 127) / 128, 1);
        fc_mma_k<<<grid, 256>>>(1, dec_fc_w, dec_fc_b, GC, LATD, 125, 125, 1);
    }

    // 5) decoder grouped conv-transpose + sigmoid -> out
    dec_conv_k<<<(B_SZ * G_CNT + 255) / 256, 256>>>(dec_w, dec_b, out);
}

// round 6
// speedup vs baseline: 2.4368x; 1.8794x over previous
#include <cuda_runtime.h>
#include <math.h>
#include <stdint.h>

#define B_SZ    128
#define G_CNT   10000
#define KWID    20
#define C_OUT   3
#define LATD    2000
#define GC      30000
#define IN_LEN  200000
#define NSPLIT1 16

// scratch (__device__ globals; no allocations allowed)
__device__ float g_h[B_SZ * GC];                // encoder conv out (15.36 MB)
__device__ float g_part[NSPLIT1 * B_SZ * LATD]; // FC1 split-K partials (16.4 MB)
__device__ float g_z[B_SZ * LATD];              // latent
__device__ float g_d[B_SZ * GC];                // decoder FC out

__device__ __forceinline__ float lrelu(float x) { return x >= 0.0f ? x : 0.1f * x; }

__device__ __forceinline__ uint32_t to_tf32(float x) {
    uint32_t r;
    asm("cvt.rna.tf32.f32 %0, %1;" : "=r"(r) : "f"(x));
    return r;
}

__device__ __forceinline__ void mma_tf32(float c[4], const uint32_t a[4], const uint32_t b[2]) {
    asm volatile(
        "mma.sync.aligned.m16n8k8.row.col.f32.tf32.tf32.f32 "
        "{%0,%1,%2,%3}, {%4,%5,%6,%7}, {%8,%9}, {%0,%1,%2,%3};"
        : "+f"(c[0]), "+f"(c[1]), "+f"(c[2]), "+f"(c[3])
        : "r"(a[0]), "r"(a[1]), "r"(a[2]), "r"(a[3]), "r"(b[0]), "r"(b[1]));
}

// ---------------------------------------------------------------------------
// Kernel 1: grouped encoder conv  h[b,g,c] = lrelu(sum_k x[b,g*20+k]*w[g,c,k]+b)
// ---------------------------------------------------------------------------
__global__ __launch_bounds__(256) void enc_conv_k(
    const float* __restrict__ x, const float* __restrict__ w, const float* __restrict__ bias)
{
    int idx = blockIdx.x * blockDim.x + threadIdx.x;
    if (idx >= B_SZ * G_CNT) return;
    int b = idx / G_CNT, g = idx % G_CNT;

    const float4* xp = (const float4*)(x + (size_t)b * IN_LEN + g * KWID);
    float xv[20];
#pragma unroll
    for (int i = 0; i < 5; i++) {
        float4 t = xp[i];
        xv[4*i+0] = t.x; xv[4*i+1] = t.y; xv[4*i+2] = t.z; xv[4*i+3] = t.w;
    }
    const float* wp = w + (size_t)g * (C_OUT * KWID);
    float* hp = g_h + (size_t)b * GC + (size_t)g * C_OUT;
#pragma unroll
    for (int c = 0; c < C_OUT; c++) {
        const float4* wc = (const float4*)(wp + c * KWID);
        float acc = bias[g * C_OUT + c];
#pragma unroll
        for (int i = 0; i < 5; i++) {
            float4 t = wc[i];
            acc = fmaf(xv[4*i+0], t.x, acc);
            acc = fmaf(xv[4*i+1], t.y, acc);
            acc = fmaf(xv[4*i+2], t.z, acc);
            acc = fmaf(xv[4*i+3], t.w, acc);
        }
        hp[c] = lrelu(acc);
    }
}

// ---------------------------------------------------------------------------
// FC GEMM via mma.sync tf32 (single-pass, cvt.rna conversion -> rel_err ~1e-4).
// C[m,n] = sum_k A[m,k]*W[n,k]; A row-major [128,K], W row-major [N,K].
// Block tile 128(M) x 128(N), BK=16, 256 threads = 8 warps (2x4).
// __launch_bounds__(256,2) caps regs at 128 -> 2 CTAs/SM for latency hiding.
// fuse==0: raw split-K partials -> g_part[(sp*128+m)*N+n]   (FC1)
// fuse==1: lrelu(acc + bias[n]) -> g_d                       (FC2)
// which: 0 -> A=g_h, 1 -> A=g_z
// ---------------------------------------------------------------------------
__global__ __launch_bounds__(256, 2) void fc_mma_k(
    int which, const float* __restrict__ W, const float* __restrict__ bias,
    int N, int K, int steps_total, int steps_per_split, int fuse)
{
    __shared__ uint32_t Ah[16][136];
    __shared__ uint32_t Wh[16][136];

    const float* __restrict__ A = (which == 0) ? g_h : g_z;

    const int tid = threadIdx.x;
    const int nbase = blockIdx.x * 128;
    const int sp = blockIdx.y;
    int s0 = sp * steps_per_split;
    int s1 = s0 + steps_per_split;
    if (s1 > steps_total) s1 = steps_total;

    const int warp = tid >> 5, lane = tid & 31;
    const int wm = (warp >> 2) * 64;   // 0 or 64
    const int wn = (warp & 3) * 32;    // 0..96
    const int g = lane >> 2, tig = lane & 3;

    float acc[4][4][4];
#pragma unroll
    for (int mt = 0; mt < 4; mt++)
#pragma unroll
        for (int nt = 0; nt < 4; nt++)
#pragma unroll
            for (int v = 0; v < 4; v++) acc[mt][nt][v] = 0.0f;

    float4 ra[2], rw[2];
    const int row_a = tid >> 2;      // 0..63 (+64 for i=1)
    const int q_a   = tid & 3;       // k-quad

    {
        int k0 = s0 * 16;
#pragma unroll
        for (int i = 0; i < 2; i++) {
            int row = row_a + i * 64;
            ra[i] = *(const float4*)(A + (size_t)row * K + k0 + q_a * 4);
            int wr = nbase + row;
            rw[i] = (wr < N) ? *(const float4*)(W + (size_t)wr * K + k0 + q_a * 4)
                             : make_float4(0.f, 0.f, 0.f, 0.f);
        }
    }

    for (int st = s0; st < s1; ++st) {
        __syncthreads();
#pragma unroll
        for (int i = 0; i < 2; i++) {
            int row = row_a + i * 64;
            float va[4] = { ra[i].x, ra[i].y, ra[i].z, ra[i].w };
            float vw[4] = { rw[i].x, rw[i].y, rw[i].z, rw[i].w };
#pragma unroll
            for (int j = 0; j < 4; j++) {
                Ah[q_a * 4 + j][row] = to_tf32(va[j]);
                Wh[q_a * 4 + j][row] = to_tf32(vw[j]);
            }
        }
        __syncthreads();

        // prefetch next tile (overlaps compute)
        if (st + 1 < s1) {
            int k0 = (st + 1) * 16;
#pragma unroll
            for (int i = 0; i < 2; i++) {
                int row = row_a + i * 64;
                ra[i] = *(const float4*)(A + (size_t)row * K + k0 + q_a * 4);
                int wr = nbase + row;
                rw[i] = (wr < N) ? *(const float4*)(W + (size_t)wr * K + k0 + q_a * 4)
                                 : make_float4(0.f, 0.f, 0.f, 0.f);
            }
        }

#pragma unroll
        for (int kk = 0; kk < 2; kk++) {
            const int k = kk * 8;
            uint32_t bh[4][2];
#pragma unroll
            for (int nt = 0; nt < 4; nt++) {
                int n = wn + nt * 8 + g;
                bh[nt][0] = Wh[k + tig][n];
                bh[nt][1] = Wh[k + tig + 4][n];
            }
#pragma unroll
            for (int mt = 0; mt < 4; mt++) {
                int m = wm + mt * 16 + g;
                uint32_t ah[4];
                ah[0] = Ah[k + tig][m];     ah[1] = Ah[k + tig][m + 8];
                ah[2] = Ah[k + tig + 4][m]; ah[3] = Ah[k + tig + 4][m + 8];
#pragma unroll
                for (int nt = 0; nt < 4; nt++)
                    mma_tf32(acc[mt][nt], ah, bh[nt]);
            }
        }
    }

    // epilogue
#pragma unroll
    for (int mt = 0; mt < 4; mt++) {
        int m0 = wm + mt * 16 + g;
#pragma unroll
        for (int nt = 0; nt < 4; nt++) {
            int n = nbase + wn + nt * 8 + tig * 2;
            if (n >= N) continue;
            if (fuse) {
                float b0 = bias[n], b1 = bias[n + 1];
                float2 v0, v1;
                v0.x = lrelu(acc[mt][nt][0] + b0);
                v0.y = lrelu(acc[mt][nt][1] + b1);
                v1.x = lrelu(acc[mt][nt][2] + b0);
                v1.y = lrelu(acc[mt][nt][3] + b1);
                *(float2*)(g_d + (size_t)m0 * N + n) = v0;
                *(float2*)(g_d + (size_t)(m0 + 8) * N + n) = v1;
            } else {
                size_t base = ((size_t)(sp * B_SZ + m0)) * N + n;
                float2 v0; v0.x = acc[mt][nt][0]; v0.y = acc[mt][nt][1];
                float2 v1; v1.x = acc[mt][nt][2]; v1.y = acc[mt][nt][3];
                *(float2*)(g_part + base) = v0;
                *(float2*)(g_part + base + (size_t)8 * N) = v1;
            }
        }
    }
}

// ---------------------------------------------------------------------------
// FC1 split-K reduction + bias + leaky -> g_z
// ---------------------------------------------------------------------------
__global__ __launch_bounds__(256) void red_k(const float* __restrict__ bias)
{
    int idx = blockIdx.x * blockDim.x + threadIdx.x;
    if (idx >= B_SZ * LATD) return;
    int m = idx / LATD, n = idx % LATD;
    float s = bias[n];
#pragma unroll
    for (int sp = 0; sp < NSPLIT1; sp++)
        s += g_part[((size_t)(sp * B_SZ + m)) * LATD + n];
    g_z[(size_t)m * LATD + n] = lrelu(s);
}

// ---------------------------------------------------------------------------
// Kernel 5: grouped conv-transpose + sigmoid
// ---------------------------------------------------------------------------
__global__ __launch_bounds__(256) void dec_conv_k(
    const float* __restrict__ w, const float* __restrict__ bias, float* __restrict__ out)
{
    int idx = blockIdx.x * blockDim.x + threadIdx.x;
    if (idx >= B_SZ * G_CNT) return;
    int b = idx / G_CNT, g = idx % G_CNT;

    const float* dp = g_d + (size_t)b * GC + (size_t)g * C_OUT;
    float d0 = dp[0], d1 = dp[1], d2 = dp[2];
    const float* wp = w + (size_t)g * (C_OUT * KWID);
    float bz = bias[g];

    float o[20];
#pragma unroll
    for (int i = 0; i < 5; i++) {
        float4 w0 = ((const float4*)(wp))[i];
        float4 w1 = ((const float4*)(wp + 20))[i];
        float4 w2 = ((const float4*)(wp + 40))[i];
        float v;
        v = fmaf(d0, w0.x, fmaf(d1, w1.x, fmaf(d2, w2.x, bz))); o[4*i+0] = v;
        v = fmaf(d0, w0.y, fmaf(d1, w1.y, fmaf(d2, w2.y, bz))); o[4*i+1] = v;
        v = fmaf(d0, w0.z, fmaf(d1, w1.z, fmaf(d2, w2.z, bz))); o[4*i+2] = v;
        v = fmaf(d0, w0.w, fmaf(d1, w1.w, fmaf(d2, w2.w, bz))); o[4*i+3] = v;
    }
    float4* op = (float4*)(out + (size_t)b * IN_LEN + g * KWID);
#pragma unroll
    for (int i = 0; i < 5; i++) {
        float4 r;
        r.x = 1.0f / (1.0f + expf(-o[4*i+0]));
        r.y = 1.0f / (1.0f + expf(-o[4*i+1]));
        r.z = 1.0f / (1.0f + expf(-o[4*i+2]));
        r.w = 1.0f / (1.0f + expf(-o[4*i+3]));
        op[i] = r;
    }
}

// ---------------------------------------------------------------------------
extern "C" void kernel_launch(void* const* d_in, const int* in_sizes, int n_in,
                              void* d_out, int out_size)
{
    const float* x        = (const float*)d_in[0];
    const float* enc_w    = (const float*)d_in[1];
    const float* enc_b    = (const float*)d_in[2];
    const float* enc_fc_w = (const float*)d_in[3];
    const float* enc_fc_b = (const float*)d_in[4];
    const float* dec_fc_w = (const float*)d_in[5];
    const float* dec_fc_b = (const float*)d_in[6];
    const float* dec_w    = (const float*)d_in[7];
    const float* dec_b    = (const float*)d_in[8];
    float* out = (float*)d_out;

    // 1) encoder grouped conv -> g_h
    enc_conv_k<<<(B_SZ * G_CNT + 255) / 256, 256>>>(x, enc_w, enc_b);

    // 2) FC1: [128,30000]@[2000,30000]^T. steps=1875, split-K=16 (118/split)
    {
        dim3 grid((LATD + 127) / 128, NSPLIT1);
        fc_mma_k<<<grid, 256>>>(0, enc_fc_w, nullptr, LATD, GC, 1875, 118, 0);
    }
    // 3) reduce + bias + leaky -> g_z
    red_k<<<(B_SZ * LATD + 255) / 256, 256>>>(enc_fc_b);

    // 4) FC2: [128,2000]@[30000,2000]^T. steps=125, split=1, fused epilogue -> g_d
    {
        dim3 grid((GC + 127) / 128, 1);
        fc_mma_k<<<grid, 256>>>(1, dec_fc_w, dec_fc_b, GC, LATD, 125, 125, 1);
    }

    // 5) decoder grouped conv-transpose + sigmoid -> out
    dec_conv_k<<<(B_SZ * G_CNT + 255) / 256, 256>>>(dec_w, dec_b, out);
}

// round 15
// speedup vs baseline: 3.2156x; 1.3196x over previous
#include <cuda_runtime.h>
#include <cuda_bf16.h>
#include <math.h>
#include <stdint.h>

#define B_SZ    128
#define G_CNT   10000
#define KWID    20
#define C_OUT   3
#define LATD    2000
#define GC      30000
#define IN_LEN  200000
#define NSPLIT1 15

// scratch (__device__ globals; no allocations allowed)
__device__ float g_h[B_SZ * GC];                // encoder conv out (15.36 MB)
__device__ float g_part[NSPLIT1 * B_SZ * LATD]; // FC1 split-K partials (15.4 MB)
__device__ float g_z[B_SZ * LATD];              // latent
__device__ float g_d[B_SZ * GC];                // decoder FC out

__device__ __forceinline__ float lrelu(float x) { return x >= 0.0f ? x : 0.1f * x; }

// pack two floats into bf16x2: low half = lo (lower k index), high = hi
__device__ __forceinline__ uint32_t pack_bf16(float lo, float hi) {
    uint32_t r;
    asm("cvt.rn.bf16x2.f32 %0, %1, %2;" : "=r"(r) : "f"(hi), "f"(lo));
    return r;
}

__device__ __forceinline__ uint32_t smem_u32(const void* p) {
    uint32_t a;
    asm("{ .reg .u64 t; cvta.to.shared.u64 t, %1; cvt.u32.u64 %0, t; }" : "=r"(a) : "l"(p));
    return a;
}

__device__ __forceinline__ void ldsm4(uint32_t r[4], uint32_t addr) {
    asm volatile("ldmatrix.sync.aligned.m8n8.x4.shared.b16 {%0,%1,%2,%3}, [%4];"
                 : "=r"(r[0]), "=r"(r[1]), "=r"(r[2]), "=r"(r[3]) : "r"(addr));
}

__device__ __forceinline__ void mma_bf16(float c[4], const uint32_t a[4], const uint32_t b[2]) {
    asm volatile(
        "mma.sync.aligned.m16n8k16.row.col.f32.bf16.bf16.f32 "
        "{%0,%1,%2,%3}, {%4,%5,%6,%7}, {%8,%9}, {%0,%1,%2,%3};"
        : "+f"(c[0]), "+f"(c[1]), "+f"(c[2]), "+f"(c[3])
        : "r"(a[0]), "r"(a[1]), "r"(a[2]), "r"(a[3]), "r"(b[0]), "r"(b[1]));
}

// ---------------------------------------------------------------------------
// Kernel 1: grouped encoder conv  h[b,g,c] = lrelu(sum_k x[b,g*20+k]*w[g,c,k]+b)
// ---------------------------------------------------------------------------
__global__ __launch_bounds__(256) void enc_conv_k(
    const float* __restrict__ x, const float* __restrict__ w, const float* __restrict__ bias)
{
    int idx = blockIdx.x * blockDim.x + threadIdx.x;
    if (idx >= B_SZ * G_CNT) return;
    int b = idx / G_CNT, g = idx % G_CNT;

    const float4* xp = (const float4*)(x + (size_t)b * IN_LEN + g * KWID);
    float xv[20];
#pragma unroll
    for (int i = 0; i < 5; i++) {
        float4 t = xp[i];
        xv[4*i+0] = t.x; xv[4*i+1] = t.y; xv[4*i+2] = t.z; xv[4*i+3] = t.w;
    }
    const float* wp = w + (size_t)g * (C_OUT * KWID);
    float* hp = g_h + (size_t)b * GC + (size_t)g * C_OUT;
#pragma unroll
    for (int c = 0; c < C_OUT; c++) {
        const float4* wc = (const float4*)(wp + c * KWID);
        float acc = bias[g * C_OUT + c];
#pragma unroll
        for (int i = 0; i < 5; i++) {
            float4 t = wc[i];
            acc = fmaf(xv[4*i+0], t.x, acc);
            acc = fmaf(xv[4*i+1], t.y, acc);
            acc = fmaf(xv[4*i+2], t.z, acc);
            acc = fmaf(xv[4*i+3], t.w, acc);
        }
        hp[c] = lrelu(acc);
    }
}

// ---------------------------------------------------------------------------
// FC GEMM via bf16 mma.sync m16n8k16 + ldmatrix.
// C[m,n] = sum_k A[m,k]*W[n,k]; A row-major [128,K], W row-major [N,K].
// Block tile 128x128, BK=64 floats, smem tile = 128 rows x 128B bf16,
// chunk-swizzle c^(r&7). Double-buffered, 1 sync/step. 8 warps (2m x 4n).
// fuse==0: raw partials -> g_part[(sp*128+m)*N+n]   (FC1)
// fuse==1: lrelu(acc+bias[n]) -> g_d                 (FC2)
// ---------------------------------------------------------------------------
extern __shared__ __align__(128) char smem_raw[];   // 2 stages x (16KB A + 16KB B)
#define SMEM_BYTES 65536

__global__ __launch_bounds__(256, 2) void fc_bf16_k(
    int which, const float* __restrict__ W, const float* __restrict__ bias,
    int N, int K, int steps_total, int steps_per_split, int fuse)
{
    const float* __restrict__ A = which ? g_z : g_h;
    const int tid = threadIdx.x, warp = tid >> 5, lane = tid & 31;
    const int nbase = blockIdx.x * 128, sp = blockIdx.y;
    int s0 = sp * steps_per_split;
    int s1 = s0 + steps_per_split;
    if (s1 > steps_total) s1 = steps_total;

    const int wm = (warp >> 2) * 64;   // 0 or 64
    const int wn = (warp & 3) * 32;    // 0..96
    const int g = lane >> 2, tig = lane & 3;
    const uint32_t smb = smem_u32(smem_raw);

    float acc[4][4][4];
#pragma unroll
    for (int mt = 0; mt < 4; mt++)
#pragma unroll
        for (int nt = 0; nt < 4; nt++)
#pragma unroll
            for (int v = 0; v < 4; v++) acc[mt][nt][v] = 0.0f;

    // -------- tile loader: fp32 global -> bf16 swizzled smem --------
    const int lr0 = tid >> 3;    // 0..31 (base row)
    const int lc  = tid & 7;     // 16B chunk (8 bf16 = 8 k-floats)
    auto load_tile = [&](int st, int buf) {
        const int k0 = st * 64;
        char* da = smem_raw + buf * 32768;
        char* db = da + 16384;
        const int kf = k0 + lc * 8;
        const bool k0ok = (kf < K), k1ok = (kf + 4 < K);
#pragma unroll
        for (int i = 0; i < 4; i++) {
            int r = lr0 + i * 32;
            float4 z = make_float4(0.f, 0.f, 0.f, 0.f);
            float4 v0 = z, v1 = z, w0 = z, w1 = z;
            if (k0ok) v0 = *(const float4*)(A + (size_t)r * K + kf);
            if (k1ok) v1 = *(const float4*)(A + (size_t)r * K + kf + 4);
            int wr = nbase + r;
            if (wr < N) {
                if (k0ok) w0 = *(const float4*)(W + (size_t)wr * K + kf);
                if (k1ok) w1 = *(const float4*)(W + (size_t)wr * K + kf + 4);
            }
            uint4 pa, pb;
            pa.x = pack_bf16(v0.x, v0.y); pa.y = pack_bf16(v0.z, v0.w);
            pa.z = pack_bf16(v1.x, v1.y); pa.w = pack_bf16(v1.z, v1.w);
            pb.x = pack_bf16(w0.x, w0.y); pb.y = pack_bf16(w0.z, w0.w);
            pb.z = pack_bf16(w1.x, w1.y); pb.w = pack_bf16(w1.z, w1.w);
            int off = r * 128 + ((lc ^ (r & 7)) * 16);
            *(uint4*)(da + off) = pa;
            *(uint4*)(db + off) = pb;
        }
    };

    // per-lane ldmatrix row/chunk components
    const int a_lrow = (lane & 7) + ((lane >> 3) & 1) * 8;  // + wm + mt*16
    const int a_lk   = (lane >> 4) & 1;                      // k-half chunk
    const int b_mi   = lane >> 3;                            // matrix index 0..3
    const int b_lrow = lane & 7;                             // + wn + nt*8

    load_tile(s0, 0);
    __syncthreads();

    for (int st = s0; st < s1; ++st) {
        const int buf = (st - s0) & 1;
        if (st + 1 < s1) load_tile(st + 1, buf ^ 1);

        const uint32_t abase = smb + buf * 32768;
        const uint32_t bbase = abase + 16384;
#pragma unroll
        for (int kb = 0; kb < 4; kb++) {
            uint32_t af[4][4];
#pragma unroll
            for (int mt = 0; mt < 4; mt++) {
                int row = wm + mt * 16 + a_lrow;
                int ch  = 2 * kb + a_lk;
                ldsm4(af[mt], abase + row * 128 + ((ch ^ (row & 7)) * 16));
            }
            uint32_t bf[4][2];
#pragma unroll
            for (int half = 0; half < 2; half++) {
                int nt  = half * 2 + (b_mi >> 1);
                int h   = b_mi & 1;
                int row = wn + nt * 8 + b_lrow;
                int ch  = 2 * kb + h;
                uint32_t t[4];
                ldsm4(t, bbase + row * 128 + ((ch ^ (row & 7)) * 16));
                bf[half * 2 + 0][0] = t[0]; bf[half * 2 + 0][1] = t[1];
                bf[half * 2 + 1][0] = t[2]; bf[half * 2 + 1][1] = t[3];
            }
#pragma unroll
            for (int mt = 0; mt < 4; mt++)
#pragma unroll
                for (int nt = 0; nt < 4; nt++)
                    mma_bf16(acc[mt][nt], af[mt], bf[nt]);
        }
        __syncthreads();
    }

    // -------- epilogue --------
#pragma unroll
    for (int mt = 0; mt < 4; mt++) {
        int m0 = wm + mt * 16 + g;
#pragma unroll
        for (int nt = 0; nt < 4; nt++) {
            int n = nbase + wn + nt * 8 + tig * 2;
            if (n >= N) continue;
            if (fuse) {
                float b0 = bias[n], b1 = bias[n + 1];
                float2 v0, v1;
                v0.x = lrelu(acc[mt][nt][0] + b0);
                v0.y = lrelu(acc[mt][nt][1] + b1);
                v1.x = lrelu(acc[mt][nt][2] + b0);
                v1.y = lrelu(acc[mt][nt][3] + b1);
                *(float2*)(g_d + (size_t)m0 * N + n) = v0;
                *(float2*)(g_d + (size_t)(m0 + 8) * N + n) = v1;
            } else {
                size_t base = ((size_t)(sp * B_SZ + m0)) * N + n;
                float2 v0; v0.x = acc[mt][nt][0]; v0.y = acc[mt][nt][1];
                float2 v1; v1.x = acc[mt][nt][2]; v1.y = acc[mt][nt][3];
                *(float2*)(g_part + base) = v0;
                *(float2*)(g_part + base + (size_t)8 * N) = v1;
            }
        }
    }
}

// ---------------------------------------------------------------------------
// FC1 split-K reduction + bias + leaky -> g_z
// ---------------------------------------------------------------------------
__global__ __launch_bounds__(256) void red_k(const float* __restrict__ bias)
{
    int idx = blockIdx.x * blockDim.x + threadIdx.x;
    if (idx >= B_SZ * LATD) return;
    int m = idx / LATD, n = idx % LATD;
    float s = bias[n];
#pragma unroll
    for (int sp = 0; sp < NSPLIT1; sp++)
        s += g_part[((size_t)(sp * B_SZ + m)) * LATD + n];
    g_z[(size_t)m * LATD + n] = lrelu(s);
}

// ---------------------------------------------------------------------------
// Kernel 5: grouped conv-transpose + sigmoid
// ---------------------------------------------------------------------------
__global__ __launch_bounds__(256) void dec_conv_k(
    const float* __restrict__ w, const float* __restrict__ bias, float* __restrict__ out)
{
    int idx = blockIdx.x * blockDim.x + threadIdx.x;
    if (idx >= B_SZ * G_CNT) return;
    int b = idx / G_CNT, g = idx % G_CNT;

    const float* dp = g_d + (size_t)b * GC + (size_t)g * C_OUT;
    float d0 = dp[0], d1 = dp[1], d2 = dp[2];
    const float* wp = w + (size_t)g * (C_OUT * KWID);
    float bz = bias[g];

    float o[20];
#pragma unroll
    for (int i = 0; i < 5; i++) {
        float4 w0 = ((const float4*)(wp))[i];
        float4 w1 = ((const float4*)(wp + 20))[i];
        float4 w2 = ((const float4*)(wp + 40))[i];
        float v;
        v = fmaf(d0, w0.x, fmaf(d1, w1.x, fmaf(d2, w2.x, bz))); o[4*i+0] = v;
        v = fmaf(d0, w0.y, fmaf(d1, w1.y, fmaf(d2, w2.y, bz))); o[4*i+1] = v;
        v = fmaf(d0, w0.z, fmaf(d1, w1.z, fmaf(d2, w2.z, bz))); o[4*i+2] = v;
        v = fmaf(d0, w0.w, fmaf(d1, w1.w, fmaf(d2, w2.w, bz))); o[4*i+3] = v;
    }
    float4* op = (float4*)(out + (size_t)b * IN_LEN + g * KWID);
#pragma unroll
    for (int i = 0; i < 5; i++) {
        float4 r;
        r.x = 1.0f / (1.0f + expf(-o[4*i+0]));
        r.y = 1.0f / (1.0f + expf(-o[4*i+1]));
        r.z = 1.0f / (1.0f + expf(-o[4*i+2]));
        r.w = 1.0f / (1.0f + expf(-o[4*i+3]));
        op[i] = r;
    }
}

// ---------------------------------------------------------------------------
extern "C" void kernel_launch(void* const* d_in, const int* in_sizes, int n_in,
                              void* d_out, int out_size)
{
    const float* x        = (const float*)d_in[0];
    const float* enc_w    = (const float*)d_in[1];
    const float* enc_b    = (const float*)d_in[2];
    const float* enc_fc_w = (const float*)d_in[3];
    const float* enc_fc_b = (const float*)d_in[4];
    const float* dec_fc_w = (const float*)d_in[5];
    const float* dec_fc_b = (const float*)d_in[6];
    const float* dec_w    = (const float*)d_in[7];
    const float* dec_b    = (const float*)d_in[8];
    float* out = (float*)d_out;

    // idempotent, non-stream API (safe under graph capture)
    cudaFuncSetAttribute(fc_bf16_k, cudaFuncAttributeMaxDynamicSharedMemorySize, SMEM_BYTES);

    // 1) encoder grouped conv -> g_h
    enc_conv_k<<<(B_SZ * G_CNT + 255) / 256, 256>>>(x, enc_w, enc_b);

    // 2) FC1: [128,30000]@[2000,30000]^T. 469 BK64-steps, split 15 x 32.
    {
        dim3 grid((LATD + 127) / 128, NSPLIT1);
        fc_bf16_k<<<grid, 256, SMEM_BYTES>>>(0, enc_fc_w, nullptr, LATD, GC, 469, 32, 0);
    }
    // 3) reduce + bias + leaky -> g_z
    red_k<<<(B_SZ * LATD + 255) / 256, 256>>>(enc_fc_b);

    // 4) FC2: [128,2000]@[30000,2000]^T. 32 BK64-steps, unsplit, fused -> g_d
    {
        dim3 grid((GC + 127) / 128, 1);
        fc_bf16_k<<<grid, 256, SMEM_BYTES>>>(1, dec_fc_w, dec_fc_b, GC, LATD, 32, 32, 1);
    }

    // 5) decoder grouped conv-transpose + sigmoid -> out
    dec_conv_k<<<(B_SZ * G_CNT + 255) / 256, 256>>>(dec_w, dec_b, out);
}